// round 15
// baseline (speedup 1.0000x reference)
#include <cuda_runtime.h>
#include <cstdint>

// ERGCN layer:
//   msg[k] = h[src[k]] * weight[rel[k]] + e[k] * attention[rel[k]]   (D=64)
//   out    = h + segment_sum(msg, dst)
//
// Inputs: h[N*64] f32, e[E*64] f32, weight[R*64] f32, attention[R*64] f32,
//         src[E] i32, dst[E] i32, rel[E] i32. Output: [N*64] f32.

#define D 64
#define D4 (D / 4)            // 16 float4 per row
#define TPB 256
#define EPT (TPB / 8)         // 32 edges per tile (8 threads/edge)
#define ROW_BYTES 256         // one e row
#define TILE_BYTES (EPT * ROW_BYTES)   // 8192
#define NBLOCKS (148 * 5)     // persistent, one wave at 5 CTAs/SM

__device__ __forceinline__ void red_add_v4(float* o, float4 m) {
    asm volatile("red.global.add.v4.f32 [%0], {%1, %2, %3, %4};"
                 :: "l"(o), "f"(m.x), "f"(m.y), "f"(m.z), "f"(m.w)
                 : "memory");
}

__device__ __forceinline__ uint32_t smem_u32(const void* p) {
    uint32_t a;
    asm("{ .reg .u64 t; cvta.to.shared.u64 t, %1; cvt.u32.u64 %0, t; }"
        : "=r"(a) : "l"(p));
    return a;
}

__device__ __forceinline__ void mbar_init(uint32_t mbar, uint32_t cnt) {
    asm volatile("mbarrier.init.shared.b64 [%0], %1;" :: "r"(mbar), "r"(cnt)
                 : "memory");
}

__device__ __forceinline__ void mbar_expect_tx(uint32_t mbar, uint32_t bytes) {
    asm volatile("mbarrier.arrive.expect_tx.shared.b64 _, [%0], %1;"
                 :: "r"(mbar), "r"(bytes) : "memory");
}

__device__ __forceinline__ void bulk_g2s(uint32_t dst_smem, const void* src,
                                         uint32_t bytes, uint32_t mbar) {
    asm volatile("cp.async.bulk.shared::cta.global.mbarrier::complete_tx::bytes "
                 "[%0], [%1], %2, [%3];"
                 :: "r"(dst_smem), "l"(src), "r"(bytes), "r"(mbar) : "memory");
}

__device__ __forceinline__ void mbar_wait(uint32_t mbar, int parity) {
    asm volatile(
        "{\n\t.reg .pred P;\n"
        "W%=:\n\t"
        "mbarrier.try_wait.parity.acquire.cta.shared::cta.b64 P, [%0], %1;\n\t"
        "@!P bra W%=;\n\t}"
        :: "r"(mbar), "r"(parity) : "memory");
}

// ---------------------------------------------------------------------------
// Kernel 1: out = h (d_out is poisoned before timing)
// ---------------------------------------------------------------------------
__global__ void init_out_kernel(float4* __restrict__ out,
                                const float4* __restrict__ h,
                                int n4) {
    int i = blockIdx.x * blockDim.x + threadIdx.x;
    if (i < n4) out[i] = h[i];
}

// ---------------------------------------------------------------------------
// Kernel 2: persistent tiles of 32 edges. e-stream arrives via cp.async.bulk
// into double-buffered smem (off the l1tex LDG path); idx prefetched at
// distance 1; h/w/a gathered by LDG; RED.128 scatter.
// ---------------------------------------------------------------------------
__global__ void __launch_bounds__(TPB)
edge_kernel(const float* __restrict__ h,
            const float* __restrict__ e,
            const float4* __restrict__ w_g,
            const float4* __restrict__ a_g,
            const int* __restrict__ src,
            const int* __restrict__ dst,
            const int* __restrict__ rel,
            float* __restrict__ out,
            int E_) {
    __shared__ __align__(1024) char ebuf[2][TILE_BYTES];
    __shared__ __align__(16) uint64_t mbar_s[2];

    const int tid   = threadIdx.x;
    const int t     = tid & 7;          // chunk (t and t+8)
    const int group = tid >> 3;         // edge within tile
    const int ntiles = (E_ + EPT - 1) / EPT;

    const uint32_t mb[2] = { smem_u32(&mbar_s[0]), smem_u32(&mbar_s[1]) };
    const uint32_t eb[2] = { smem_u32(&ebuf[0][0]), smem_u32(&ebuf[1][0]) };

    if (tid == 0) {
        mbar_init(mb[0], 1);
        mbar_init(mb[1], 1);
        asm volatile("fence.proxy.async.shared::cta;" ::: "memory");
    }
    __syncthreads();

    int j = blockIdx.x;                 // tile index; strides by NBLOCKS
    if (j >= ntiles) return;

    // Prologue: issue tile j's e bulk copy into buf 0; prefetch its indices.
    if (tid == 0) {
        int base = j * EPT;
        uint32_t nb = (uint32_t)(min(EPT, E_ - base)) * ROW_BYTES;
        mbar_expect_tx(mb[0], nb);
        bulk_g2s(eb[0], (const char*)e + (size_t)base * ROW_BYTES, nb, mb[0]);
    }
    int k = j * EPT + group;
    bool valid = k < E_;
    int kc = valid ? k : 0;
    int s_ = __ldg(src + kc);
    int d_ = __ldg(dst + kc);
    int r_ = __ldg(rel + kc);

    int buf = 0;
    int ph0 = 0, ph1 = 0;

    while (true) {
        const int jn = j + NBLOCKS;
        const bool more = jn < ntiles;

        // Issue next tile's bulk copy into the other buffer (consumed two
        // iterations ago; __syncthreads below guarantees reuse safety).
        if (more && tid == 0) {
            int base = jn * EPT;
            uint32_t nb = (uint32_t)(min(EPT, E_ - base)) * ROW_BYTES;
            mbar_expect_tx(mb[buf ^ 1], nb);
            bulk_g2s(eb[buf ^ 1], (const char*)e + (size_t)base * ROW_BYTES,
                     nb, mb[buf ^ 1]);
        }
        // Prefetch next tile's indices.
        const int kn = jn * EPT + group;
        const bool vn = more && kn < E_;
        const int kcn = vn ? kn : 0;
        const int sn = __ldg(src + kcn);
        const int dn = __ldg(dst + kcn);
        const int rn = __ldg(rel + kcn);

        // Wait for the current e tile.
        int phc = buf ? ph1 : ph0;
        mbar_wait(mb[buf], phc);
        if (buf) ph1 ^= 1; else ph0 ^= 1;

        // Compute + scatter (indices resolved one iteration ago).
        if (valid) {
            const float4* es = (const float4*)(&ebuf[buf][group * ROW_BYTES]);
            const float4 ev0 = es[t];
            const float4 ev1 = es[t + 8];

            const float4* hp = (const float4*)(h + (size_t)s_ * D) + t;
            const float4* wp = w_g + r_ * D4 + t;
            const float4* ap = a_g + r_ * D4 + t;
            const float4 hv0 = __ldg(hp);
            const float4 hv1 = __ldg(hp + 8);
            const float4 wv0 = __ldg(wp);
            const float4 wv1 = __ldg(wp + 8);
            const float4 av0 = __ldg(ap);
            const float4 av1 = __ldg(ap + 8);

            float4 m0, m1;
            m0.x = fmaf(hv0.x, wv0.x, ev0.x * av0.x);
            m0.y = fmaf(hv0.y, wv0.y, ev0.y * av0.y);
            m0.z = fmaf(hv0.z, wv0.z, ev0.z * av0.z);
            m0.w = fmaf(hv0.w, wv0.w, ev0.w * av0.w);
            m1.x = fmaf(hv1.x, wv1.x, ev1.x * av1.x);
            m1.y = fmaf(hv1.y, wv1.y, ev1.y * av1.y);
            m1.z = fmaf(hv1.z, wv1.z, ev1.z * av1.z);
            m1.w = fmaf(hv1.w, wv1.w, ev1.w * av1.w);

            float* o = out + (size_t)d_ * D + t * 4;
            red_add_v4(o, m0);
            red_add_v4(o + 32, m1);
        }

        __syncthreads();   // all warps done reading ebuf[buf] before reuse

        if (!more) break;
        j = jn; buf ^= 1;
        valid = vn; s_ = sn; d_ = dn; r_ = rn;
    }
}

extern "C" void kernel_launch(void* const* d_in, const int* in_sizes, int n_in,
                              void* d_out, int out_size) {
    const float* h   = (const float*)d_in[0];
    const float* e   = (const float*)d_in[1];
    const float* wgt = (const float*)d_in[2];
    const float* att = (const float*)d_in[3];
    const int*   src = (const int*)d_in[4];
    const int*   dst = (const int*)d_in[5];
    const int*   rel = (const int*)d_in[6];
    float*       out = (float*)d_out;

    const int ND = in_sizes[0];      // N * 64
    const int E_ = in_sizes[4];      // edge count

    // out = h
    {
        int n4 = ND / 4;
        init_out_kernel<<<(n4 + 255) / 256, 256>>>(
            (float4*)out, (const float4*)h, n4);
    }

    // persistent TMA-fed edge kernel
    edge_kernel<<<NBLOCKS, TPB>>>(h, e, (const float4*)wgt,
                                  (const float4*)att,
                                  src, dst, rel, out, E_);
}

// round 17
// speedup vs baseline: 1.2839x; 1.2839x over previous
#include <cuda_runtime.h>
#include <cstdint>

// ERGCN layer:
//   msg[k] = h[src[k]] * weight[rel[k]] + e[k] * attention[rel[k]]   (D=64)
//   out    = h + segment_sum(msg, dst)
//
// Inputs: h[N*64] f32, e[E*64] f32, weight[R*64] f32, attention[R*64] f32,
//         src[E] i32, dst[E] i32, rel[E] i32. Output: [N*64] f32.

#define D 64
#define D4 (D / 4)          // 16 float4 per row
#define TPB 256
#define EPB (TPB / 8)       // 32 edges per block-iteration (8 threads/edge)
#define NBLOCKS (148 * 3)   // one wave at 3 CTAs/SM (~80 regs/thread)

// e stream: bypass L1 allocation (zero reuse; keep tables/h resident in L1).
__device__ __forceinline__ float4 ldg_stream(const float4* p) {
    float4 v;
    asm("ld.global.nc.L1::no_allocate.v4.f32 {%0,%1,%2,%3}, [%4];"
        : "=f"(v.x), "=f"(v.y), "=f"(v.z), "=f"(v.w) : "l"(p));
    return v;
}

__device__ __forceinline__ void red_add_v4(float* o, float4 m) {
    asm volatile("red.global.add.v4.f32 [%0], {%1, %2, %3, %4};"
                 :: "l"(o), "f"(m.x), "f"(m.y), "f"(m.z), "f"(m.w)
                 : "memory");
}

// ---------------------------------------------------------------------------
// Kernel 1: out = h (d_out is poisoned before timing)
// ---------------------------------------------------------------------------
__global__ void init_out_kernel(float4* __restrict__ out,
                                const float4* __restrict__ h,
                                int n4) {
    int i = blockIdx.x * blockDim.x + threadIdx.x;
    if (i < n4) out[i] = h[i];
}

// ---------------------------------------------------------------------------
// Kernel 2: 8 threads/edge, persistent grid-stride, 3-stage pipeline:
//   stage C: indices at distance 2
//   stage B: ALL data loads (e, h, w, a) at distance 1
//   stage A: compute + RED at distance 0
// R15 bug fixed: stage B's e-row index is recomputed every iteration
// (was a stale prologue variable).
// ---------------------------------------------------------------------------
__global__ void __launch_bounds__(TPB, 3)
edge_kernel(const float* __restrict__ h,
            const float* __restrict__ e,
            const float4* __restrict__ w_g,
            const float4* __restrict__ a_g,
            const int* __restrict__ src,
            const int* __restrict__ dst,
            const int* __restrict__ rel,
            float* __restrict__ out,
            int E_) {
    const int t      = threadIdx.x & 7;            // chunk (t and t+8)
    const int group  = threadIdx.x >> 3;           // edge within block tile
    const int stride = NBLOCKS * EPB;

    const int k0 = blockIdx.x * EPB + group;
    if (k0 >= E_) return;

    // ---- Prologue: stage A (edge k0) fully loaded ----
    int dA;
    float4 evA0, evA1, hvA0, hvA1, wvA0, wvA1, avA0, avA1;
    {
        const int sA = __ldg(src + k0);
        dA           = __ldg(dst + k0);
        const int rA = __ldg(rel + k0);
        const float4* ep = (const float4*)(e + (size_t)k0 * D) + t;
        evA0 = ldg_stream(ep);   evA1 = ldg_stream(ep + 8);
        const float4* hp = (const float4*)(h + (size_t)sA * D) + t;
        hvA0 = __ldg(hp);        hvA1 = __ldg(hp + 8);
        const float4* wp = w_g + rA * D4 + t;
        wvA0 = __ldg(wp);        wvA1 = __ldg(wp + 8);
        const float4* ap = a_g + rA * D4 + t;
        avA0 = __ldg(ap);        avA1 = __ldg(ap + 8);
    }

    // ---- Prologue: stage B indices (edge k0 + stride) ----
    int kB = k0 + stride;
    bool vB = kB < E_;
    {
        const int kBc0 = vB ? kB : k0;
        // indices loaded below in first loop iteration pattern
    }
    int sB, dB, rB;
    {
        const int kBc = vB ? kB : k0;
        sB = __ldg(src + kBc);
        dB = __ldg(dst + kBc);
        rB = __ldg(rel + kBc);
    }

    while (true) {
        // ---- Stage C: indices at distance 2 ----
        const int kC = kB + stride;
        const bool vC = kC < E_;
        const int kCc = vC ? kC : k0;
        const int sC = __ldg(src + kCc);
        const int dC = __ldg(dst + kCc);
        const int rC = __ldg(rel + kCc);

        // ---- Stage B: issue ALL data loads at distance 1 ----
        const int kBcur = vB ? kB : k0;            // FIX: recompute each iter
        const float4* epB = (const float4*)(e + (size_t)kBcur * D) + t;
        const float4 evB0 = ldg_stream(epB);
        const float4 evB1 = ldg_stream(epB + 8);
        const float4* hpB = (const float4*)(h + (size_t)sB * D) + t;
        const float4 hvB0 = __ldg(hpB);
        const float4 hvB1 = __ldg(hpB + 8);
        const float4* wpB = w_g + rB * D4 + t;
        const float4 wvB0 = __ldg(wpB);
        const float4 wvB1 = __ldg(wpB + 8);
        const float4* apB = a_g + rB * D4 + t;
        const float4 avB0 = __ldg(apB);
        const float4 avB1 = __ldg(apB + 8);

        // ---- Stage A: consume (loads issued a full iteration ago) ----
        {
            float4 m0, m1;
            m0.x = fmaf(hvA0.x, wvA0.x, evA0.x * avA0.x);
            m0.y = fmaf(hvA0.y, wvA0.y, evA0.y * avA0.y);
            m0.z = fmaf(hvA0.z, wvA0.z, evA0.z * avA0.z);
            m0.w = fmaf(hvA0.w, wvA0.w, evA0.w * avA0.w);
            m1.x = fmaf(hvA1.x, wvA1.x, evA1.x * avA1.x);
            m1.y = fmaf(hvA1.y, wvA1.y, evA1.y * avA1.y);
            m1.z = fmaf(hvA1.z, wvA1.z, evA1.z * avA1.z);
            m1.w = fmaf(hvA1.w, wvA1.w, evA1.w * avA1.w);
            float* o = out + (size_t)dA * D + t * 4;
            red_add_v4(o, m0);
            red_add_v4(o + 32, m1);
        }

        if (!vB) break;

        // ---- Rotate: A <- B (data), B <- C (indices) ----
        dA = dB;
        evA0 = evB0; evA1 = evB1;
        hvA0 = hvB0; hvA1 = hvB1;
        wvA0 = wvB0; wvA1 = wvB1;
        avA0 = avB0; avA1 = avB1;
        kB = kC; vB = vC; sB = sC; dB = dC; rB = rC;
    }
}

extern "C" void kernel_launch(void* const* d_in, const int* in_sizes, int n_in,
                              void* d_out, int out_size) {
    const float* h   = (const float*)d_in[0];
    const float* e   = (const float*)d_in[1];
    const float* wgt = (const float*)d_in[2];
    const float* att = (const float*)d_in[3];
    const int*   src = (const int*)d_in[4];
    const int*   dst = (const int*)d_in[5];
    const int*   rel = (const int*)d_in[6];
    float*       out = (float*)d_out;

    const int ND = in_sizes[0];      // N * 64
    const int E_ = in_sizes[4];      // edge count

    // out = h
    {
        int n4 = ND / 4;
        init_out_kernel<<<(n4 + 255) / 256, 256>>>(
            (float4*)out, (const float4*)h, n4);
    }

    // persistent fully-pipelined edge kernel, one wave at 3 CTAs/SM
    edge_kernel<<<NBLOCKS, TPB>>>(h, e, (const float4*)wgt,
                                  (const float4*)att,
                                  src, dst, rel, out, E_);
}